// round 14
// baseline (speedup 1.0000x reference)
#include <cuda_runtime.h>
#include <cuda_fp16.h>
#include <cstdint>

#define N_TOK 16384
#define DIM   2048
#define NEXP  64
#define KSEL  9
#define ERF_SCALE 45.25483399593904f   // 64/sqrt(2)

#define BK      32
#define NCHUNK  (DIM / BK)             // 64
#define LDH     40                     // smem row stride in halves (80B)
#define ATILE_H (128 * LDH)            // halves per operand buffer
#define LO_SCALE   2048.0f
#define INV_LO     (1.0f / 2048.0f)

// stage needs 128*132*4 = 67584 B; pipe needs 4*128*40*2 = 40960 B
#define SMEM_DYN_BYTES 69632

// pre-transposed, fp16-split W: [n][k], n: 0..63 Wr, 64..127 Wn. lo scaled by 2048.
__device__ __half g_Wt_hi[128 * DIM];
__device__ __half g_Wt_lo[128 * DIM];

// ---------------- helpers ----------------
__device__ __forceinline__ uint32_t smem_u32(const void* p) {
    return (uint32_t)__cvta_generic_to_shared((void*)p);
}

#define LDSM_X4(r0, r1, r2, r3, addr) \
    asm volatile("ldmatrix.sync.aligned.m8n8.x4.shared.b16 {%0,%1,%2,%3}, [%4];" \
        : "=r"(r0), "=r"(r1), "=r"(r2), "=r"(r3) : "r"(addr))

#define MMA16816(d, a, b) \
    asm volatile("mma.sync.aligned.m16n8k16.row.col.f32.f16.f16.f32 " \
        "{%0,%1,%2,%3}, {%4,%5,%6,%7}, {%8,%9}, {%0,%1,%2,%3};" \
        : "+f"((d)[0]), "+f"((d)[1]), "+f"((d)[2]), "+f"((d)[3]) \
        : "r"((a)[0]), "r"((a)[1]), "r"((a)[2]), "r"((a)[3]), \
          "r"((b)[0]), "r"((b)[1]))

__device__ __forceinline__ unsigned int ordkey(float f) {
    unsigned int b = __float_as_uint(f);
    return (b & 0x80000000u) ? ~b : (b | 0x80000000u);
}
__device__ __forceinline__ float ordinv(unsigned int u) {
    return __uint_as_float((u & 0x80000000u) ? (u ^ 0x80000000u) : ~u);
}
__device__ __forceinline__ float warp_max_f(float v) {
    #pragma unroll
    for (int off = 16; off; off >>= 1) v = fmaxf(v, __shfl_xor_sync(0xffffffffu, v, off));
    return v;
}
__device__ __forceinline__ float warp_sum_f(float v) {
    #pragma unroll
    for (int off = 16; off; off >>= 1) v += __shfl_xor_sync(0xffffffffu, v, off);
    return v;
}

// ---------------- aux kernels ----------------
__global__ void zero_tail_kernel(float* __restrict__ p) {
    p[threadIdx.x] = 0.0f;   // importance[64] + load[64]
}

__global__ void prep_w_kernel(const float* __restrict__ Wr, const float* __restrict__ Wn) {
    int idx = blockIdx.x * blockDim.x + threadIdx.x;   // 0 .. 128*2048-1
    int n = idx & 127;
    int k = idx >> 7;
    float w = (n < 64) ? Wr[k * 64 + n] : Wn[k * 64 + (n - 64)];
    __half h = __float2half_rn(w);
    g_Wt_hi[(size_t)n * DIM + k] = h;
    g_Wt_lo[(size_t)n * DIM + k] = __float2half_rn((w - __half2float(h)) * LO_SCALE);
}

// ---------------- main fused kernel ----------------
__global__ __launch_bounds__(256, 1)
void moe_router_mma(const float* __restrict__ x,
                    const float* __restrict__ br,
                    const float* __restrict__ bn,
                    const float* __restrict__ neps,
                    const float* __restrict__ gum,
                    float* __restrict__ out)
{
    extern __shared__ __align__(128) char dyn_smem[];
    __shared__ float imp_s[NEXP], ld_s[NEXP];

    __half* A_hi = (__half*)dyn_smem;                 // [128][40]
    __half* A_lo = A_hi + ATILE_H;
    __half* B_hi = A_lo + ATILE_H;                    // [n=128][40]
    __half* B_lo = B_hi + ATILE_H;
    float*  stage = (float*)dyn_smem;                 // reused post-GEMM: [128][132]

    const int tid  = threadIdx.x;
    const int lane = tid & 31;
    const int wid  = tid >> 5;
    const int wm   = wid & 1;        // row half (64 rows)
    const int wn   = wid >> 1;       // col quarter (32 cols)
    const int row0 = blockIdx.x * 128;

    if (tid < NEXP)          imp_s[tid] = 0.0f;
    else if (tid < 2 * NEXP) ld_s[tid - NEXP] = 0.0f;

    // per-lane ldmatrix base addresses (bytes, shared space)
    const int grp = lane >> 3, li = lane & 7;
    const uint32_t aA  = smem_u32(A_hi) + (uint32_t)(((wm * 64 + (grp & 1) * 8 + li) * LDH + (grp >> 1) * 8) * 2);
    const uint32_t aAl = aA + ATILE_H * 2;
    const uint32_t aB  = smem_u32(B_hi) + (uint32_t)(((wn * 32 + (grp >> 1) * 8 + li) * LDH + (grp & 1) * 8) * 2);
    const uint32_t aBl = aB + ATILE_H * 2;

    float dm[4][4][4], dl[4][4][4];
    #pragma unroll
    for (int i = 0; i < 4; i++)
        #pragma unroll
        for (int j = 0; j < 4; j++)
            #pragma unroll
            for (int q = 0; q < 4; q++) { dm[i][j][q] = 0.f; dl[i][j][q] = 0.f; }

    float4 xv[4];
    uint4  bvh[2], bvl[2];

    // gmem load macros (chunk c)
    #define LDG_CHUNK(c)                                                            \
        do {                                                                        \
            _Pragma("unroll")                                                       \
            for (int t = 0; t < 4; t++) {                                           \
                int idx = tid + t * 256, r = idx >> 3, kq = idx & 7;                \
                xv[t] = *reinterpret_cast<const float4*>(                           \
                    &x[(size_t)(row0 + r) * DIM + (c) * BK + kq * 4]);              \
            }                                                                       \
            _Pragma("unroll")                                                       \
            for (int t = 0; t < 2; t++) {                                           \
                int idx = tid + t * 256, n = idx >> 2, kq = idx & 3;                \
                bvh[t] = *reinterpret_cast<const uint4*>(                           \
                    &g_Wt_hi[(size_t)n * DIM + (c) * BK + kq * 8]);                 \
                bvl[t] = *reinterpret_cast<const uint4*>(                           \
                    &g_Wt_lo[(size_t)n * DIM + (c) * BK + kq * 8]);                 \
            }                                                                       \
        } while (0)

    #define STS_CHUNK()                                                             \
        do {                                                                        \
            _Pragma("unroll")                                                       \
            for (int t = 0; t < 4; t++) {                                           \
                int idx = tid + t * 256, r = idx >> 3, kq = idx & 7;                \
                float4 v = xv[t];                                                   \
                __half2 h01 = __floats2half2_rn(v.x, v.y);                          \
                __half2 h23 = __floats2half2_rn(v.z, v.w);                          \
                __half2 l01 = __floats2half2_rn(                                    \
                    (v.x - __half2float(__low2half(h01))) * LO_SCALE,               \
                    (v.y - __half2float(__high2half(h01))) * LO_SCALE);             \
                __half2 l23 = __floats2half2_rn(                                    \
                    (v.z - __half2float(__low2half(h23))) * LO_SCALE,               \
                    (v.w - __half2float(__high2half(h23))) * LO_SCALE);             \
                uint2 uh, ul;                                                       \
                uh.x = *(uint32_t*)&h01; uh.y = *(uint32_t*)&h23;                   \
                ul.x = *(uint32_t*)&l01; ul.y = *(uint32_t*)&l23;                   \
                *reinterpret_cast<uint2*>(&A_hi[r * LDH + kq * 4]) = uh;            \
                *reinterpret_cast<uint2*>(&A_lo[r * LDH + kq * 4]) = ul;            \
            }                                                                       \
            _Pragma("unroll")                                                       \
            for (int t = 0; t < 2; t++) {                                           \
                int idx = tid + t * 256, n = idx >> 2, kq = idx & 3;                \
                *reinterpret_cast<uint4*>(&B_hi[n * LDH + kq * 8]) = bvh[t];        \
                *reinterpret_cast<uint4*>(&B_lo[n * LDH + kq * 8]) = bvl[t];        \
            }                                                                       \
        } while (0)

    // prologue
    LDG_CHUNK(0);
    STS_CHUNK();
    LDG_CHUNK(1);
    __syncthreads();

    for (int c = 0; c < NCHUNK; c++) {
        // ---- compute chunk c ----
        #pragma unroll
        for (int ks = 0; ks < 2; ks++) {
            uint32_t ah[4][4], al[4][4], bh[4][2], bl[4][2];
            #pragma unroll
            for (int it = 0; it < 4; it++) {
                uint32_t off = (uint32_t)(it * 16 * LDH * 2 + ks * 32);
                LDSM_X4(ah[it][0], ah[it][1], ah[it][2], ah[it][3], aA + off);
                LDSM_X4(al[it][0], al[it][1], al[it][2], al[it][3], aAl + off);
            }
            #pragma unroll
            for (int jp = 0; jp < 2; jp++) {
                uint32_t off = (uint32_t)(jp * 16 * LDH * 2 + ks * 32);
                LDSM_X4(bh[jp*2][0], bh[jp*2][1], bh[jp*2+1][0], bh[jp*2+1][1], aB + off);
                LDSM_X4(bl[jp*2][0], bl[jp*2][1], bl[jp*2+1][0], bl[jp*2+1][1], aBl + off);
            }
            #pragma unroll
            for (int it = 0; it < 4; it++)
                #pragma unroll
                for (int jt = 0; jt < 4; jt++) {
                    MMA16816(dm[it][jt], ah[it], bh[jt]);
                    MMA16816(dl[it][jt], ah[it], bl[jt]);
                    MMA16816(dl[it][jt], al[it], bh[jt]);
                }
        }
        __syncthreads();
        if (c < NCHUNK - 1) {
            STS_CHUNK();
            if (c < NCHUNK - 2) LDG_CHUNK(c + 2);
            __syncthreads();
        }
    }

    // ---- accums -> stage[128][132] ----
    __syncthreads();   // all ldmatrix of last chunk done before overwriting pipe
    #pragma unroll
    for (int it = 0; it < 4; it++) {
        #pragma unroll
        for (int jt = 0; jt < 4; jt++) {
            int r  = wm * 64 + it * 16 + (lane >> 2);
            int cb = wn * 32 + jt * 8 + (lane & 3) * 2;
            float v0 = fmaf(dl[it][jt][0], INV_LO, dm[it][jt][0]);
            float v1 = fmaf(dl[it][jt][1], INV_LO, dm[it][jt][1]);
            float v2 = fmaf(dl[it][jt][2], INV_LO, dm[it][jt][2]);
            float v3 = fmaf(dl[it][jt][3], INV_LO, dm[it][jt][3]);
            *reinterpret_cast<float2*>(&stage[r * 132 + cb])       = make_float2(v0, v1);
            *reinterpret_cast<float2*>(&stage[(r + 8) * 132 + cb]) = make_float2(v2, v3);
        }
    }
    __syncthreads();

    // ---- epilogue: 8 warps x 16 rows, lane = expert pair ----
    const float br1 = br[lane],      br2 = br[lane + 32];
    const float bn1 = bn[lane],      bn2 = bn[lane + 32];
    float* out_em = out;
    float* out_rp = out + (size_t)N_TOK * NEXP;

    float impAcc1 = 0.f, impAcc2 = 0.f, ldAcc1 = 0.f, ldAcc2 = 0.f;

    for (int rr = 0; rr < 16; rr++) {
        const int r    = wid * 16 + rr;
        const int grow = row0 + r;

        float raw1 = stage[r * 132 + lane]      + br1;
        float raw2 = stage[r * 132 + 32 + lane] + br2;
        float nl1  = stage[r * 132 + 64 + lane] + bn1;
        float nl2  = stage[r * 132 + 96 + lane] + bn2;

        float std1 = fmaxf(nl1, 0.f) + log1pf(expf(-fabsf(nl1))) + 0.01f;
        float std2 = fmaxf(nl2, 0.f) + log1pf(expf(-fabsf(nl2))) + 0.01f;

        float ne1 = neps[(size_t)grow * NEXP + lane];
        float ne2 = neps[(size_t)grow * NEXP + 32 + lane];
        float g1  = gum[(size_t)grow * NEXP + lane];
        float g2  = gum[(size_t)grow * NEXP + 32 + lane];

        float noisy1 = raw1 + ne1 * std1;
        float noisy2 = raw2 + ne2 * std2;

        // top-9, exact jax.lax.top_k tie semantics (lower index first)
        unsigned long long k1 =
            ((unsigned long long)ordkey(noisy1) << 6) | (unsigned long long)(63 - lane);
        unsigned long long k2 =
            ((unsigned long long)ordkey(noisy2) << 6) | (unsigned long long)(31 - lane);
        float sel1 = 0.f, sel2 = 0.f, thr = 0.f;
        #pragma unroll
        for (int it = 0; it < KSEL; it++) {
            unsigned long long loc = (k1 > k2) ? k1 : k2;
            #pragma unroll
            for (int off = 16; off; off >>= 1) {
                unsigned long long o = __shfl_xor_sync(0xffffffffu, loc, off);
                if (o > loc) loc = o;
            }
            if (it == KSEL - 1) thr = ordinv((unsigned int)(loc >> 6));
            if (k1 == loc)      { sel1 = 1.f; k1 = 0ull; }
            else if (k2 == loc) { sel2 = 1.f; k2 = 0ull; }
        }

        float m  = warp_max_f(fmaxf(noisy1, noisy2));
        float e1 = expf(noisy1 - m), e2 = expf(noisy2 - m);
        float s  = warp_sum_f(e1 + e2);
        float rp1 = e1 / s, rp2 = e2 / s;

        float ng1 = noisy1 + g1, ng2 = noisy2 + g2;
        float mg  = warp_max_f(fmaxf(ng1, ng2));
        float f1  = expf(ng1 - mg), f2 = expf(ng2 - mg);
        float sg  = warp_sum_f(f1 + f2);
        float ms1 = f1 / sg, ms2 = f2 / sg;

        float mr  = warp_max_f(fmaxf(raw1, raw2));
        float q1  = expf(raw1 - mr), q2 = expf(raw2 - mr);
        float sr  = warp_sum_f(q1 + q2);
        impAcc1 += q1 / sr;
        impAcc2 += q2 / sr;

        float a1 = (thr - raw1) / std1 * ERF_SCALE;
        float a2 = (thr - raw2) / std2 * ERF_SCALE;
        ldAcc1 += 0.5f * erfcf(a1);
        ldAcc2 += 0.5f * erfcf(a2);

        size_t ob = (size_t)grow * NEXP;
        out_em[ob + lane]      = (sel1 - ms1) + ms1;
        out_em[ob + 32 + lane] = (sel2 - ms2) + ms2;
        out_rp[ob + lane]      = rp1;
        out_rp[ob + 32 + lane] = rp2;
    }

    atomicAdd(&imp_s[lane],      impAcc1);
    atomicAdd(&imp_s[lane + 32], impAcc2);
    atomicAdd(&ld_s[lane],       ldAcc1);
    atomicAdd(&ld_s[lane + 32],  ldAcc2);

    __syncthreads();
    float* out_imp  = out + (size_t)2 * N_TOK * NEXP;
    float* out_load = out_imp + NEXP;
    if (tid < NEXP)          atomicAdd(&out_imp[tid], imp_s[tid]);
    else if (tid < 2 * NEXP) atomicAdd(&out_load[tid - NEXP], ld_s[tid - NEXP]);
}

extern "C" void kernel_launch(void* const* d_in, const int* in_sizes, int n_in,
                              void* d_out, int out_size) {
    const float* x    = (const float*)d_in[0];
    const float* Wr   = (const float*)d_in[1];
    const float* br   = (const float*)d_in[2];
    const float* Wn   = (const float*)d_in[3];
    const float* bn   = (const float*)d_in[4];
    const float* neps = (const float*)d_in[5];
    const float* gum  = (const float*)d_in[6];
    float* out = (float*)d_out;
    (void)in_sizes; (void)n_in; (void)out_size;

    static int attr_set = 0;
    if (!attr_set) {
        cudaFuncSetAttribute(moe_router_mma,
                             cudaFuncAttributeMaxDynamicSharedMemorySize, SMEM_DYN_BYTES);
        attr_set = 1;
    }

    prep_w_kernel<<<(128 * DIM) / 256, 256>>>(Wr, Wn);
    zero_tail_kernel<<<1, 128>>>(out + (size_t)2 * N_TOK * NEXP);
    moe_router_mma<<<N_TOK / 128, 256, SMEM_DYN_BYTES>>>(x, br, bn, neps, gum, out);
}

// round 15
// speedup vs baseline: 1.0061x; 1.0061x over previous
#include <cuda_runtime.h>
#include <cuda_fp16.h>
#include <cstdint>

#define N_TOK 16384
#define DIM   2048
#define NEXP  64
#define KSEL  9
#define ERF_SCALE 45.25483399593904f   // 64/sqrt(2)

#define BK      32
#define NCHUNK  (DIM / BK)             // 64
#define LDH     40                     // smem row stride in halves (80B)
#define ATILE_H (128 * LDH)            // halves per operand buffer
#define LO_SCALE   2048.0f
#define INV_LO     (1.0f / 2048.0f)

// stage needs 128*132*4 = 67584 B; pipe needs 4*128*40*2 = 40960 B
#define SMEM_DYN_BYTES 69632

// pre-transposed, fp16-split W: [n][k], n: 0..63 Wr, 64..127 Wn. lo scaled by 2048.
__device__ __half g_Wt_hi[128 * DIM];
__device__ __half g_Wt_lo[128 * DIM];

// ---------------- helpers ----------------
__device__ __forceinline__ uint32_t smem_u32(const void* p) {
    return (uint32_t)__cvta_generic_to_shared((void*)p);
}

#define LDSM_X4(r0, r1, r2, r3, addr) \
    asm volatile("ldmatrix.sync.aligned.m8n8.x4.shared.b16 {%0,%1,%2,%3}, [%4];" \
        : "=r"(r0), "=r"(r1), "=r"(r2), "=r"(r3) : "r"(addr))

#define MMA16816(d, a, b) \
    asm volatile("mma.sync.aligned.m16n8k16.row.col.f32.f16.f16.f32 " \
        "{%0,%1,%2,%3}, {%4,%5,%6,%7}, {%8,%9}, {%0,%1,%2,%3};" \
        : "+f"((d)[0]), "+f"((d)[1]), "+f"((d)[2]), "+f"((d)[3]) \
        : "r"((a)[0]), "r"((a)[1]), "r"((a)[2]), "r"((a)[3]), \
          "r"((b)[0]), "r"((b)[1]))

__device__ __forceinline__ unsigned int ordkey(float f) {
    unsigned int b = __float_as_uint(f);
    return (b & 0x80000000u) ? ~b : (b | 0x80000000u);
}
__device__ __forceinline__ float ordinv(unsigned int u) {
    return __uint_as_float((u & 0x80000000u) ? (u ^ 0x80000000u) : ~u);
}
__device__ __forceinline__ float warp_max_f(float v) {
    #pragma unroll
    for (int off = 16; off; off >>= 1) v = fmaxf(v, __shfl_xor_sync(0xffffffffu, v, off));
    return v;
}
__device__ __forceinline__ float warp_sum_f(float v) {
    #pragma unroll
    for (int off = 16; off; off >>= 1) v += __shfl_xor_sync(0xffffffffu, v, off);
    return v;
}

// ---------------- aux kernels ----------------
__global__ void zero_tail_kernel(float* __restrict__ p) {
    p[threadIdx.x] = 0.0f;   // importance[64] + load[64]
}

__global__ void prep_w_kernel(const float* __restrict__ Wr, const float* __restrict__ Wn) {
    int idx = blockIdx.x * blockDim.x + threadIdx.x;   // 0 .. 128*2048-1
    int n = idx & 127;
    int k = idx >> 7;
    float w = (n < 64) ? Wr[k * 64 + n] : Wn[k * 64 + (n - 64)];
    __half h = __float2half_rn(w);
    g_Wt_hi[(size_t)n * DIM + k] = h;
    g_Wt_lo[(size_t)n * DIM + k] = __float2half_rn((w - __half2float(h)) * LO_SCALE);
}

// ---------------- main fused kernel ----------------
__global__ __launch_bounds__(256, 1)
void moe_router_mma(const float* __restrict__ x,
                    const float* __restrict__ br,
                    const float* __restrict__ bn,
                    const float* __restrict__ neps,
                    const float* __restrict__ gum,
                    float* __restrict__ out)
{
    extern __shared__ __align__(128) char dyn_smem[];
    __shared__ float imp_s[NEXP], ld_s[NEXP];

    __half* A_hi = (__half*)dyn_smem;                 // [128][40]
    __half* A_lo = A_hi + ATILE_H;
    __half* B_hi = A_lo + ATILE_H;                    // [n=128][40]
    __half* B_lo = B_hi + ATILE_H;
    float*  stage = (float*)dyn_smem;                 // reused post-GEMM: [128][132]

    const int tid  = threadIdx.x;
    const int lane = tid & 31;
    const int wid  = tid >> 5;
    const int wm   = wid & 1;        // row half (64 rows)
    const int wn   = wid >> 1;       // col quarter (32 cols)
    const int row0 = blockIdx.x * 128;

    if (tid < NEXP)          imp_s[tid] = 0.0f;
    else if (tid < 2 * NEXP) ld_s[tid - NEXP] = 0.0f;

    // per-lane ldmatrix base addresses (bytes, shared space)
    const int grp = lane >> 3, li = lane & 7;
    const uint32_t aA  = smem_u32(A_hi) + (uint32_t)(((wm * 64 + (grp & 1) * 8 + li) * LDH + (grp >> 1) * 8) * 2);
    const uint32_t aAl = aA + ATILE_H * 2;
    const uint32_t aB  = smem_u32(B_hi) + (uint32_t)(((wn * 32 + (grp >> 1) * 8 + li) * LDH + (grp & 1) * 8) * 2);
    const uint32_t aBl = aB + ATILE_H * 2;

    float dm[4][4][4], dl[4][4][4];
    #pragma unroll
    for (int i = 0; i < 4; i++)
        #pragma unroll
        for (int j = 0; j < 4; j++)
            #pragma unroll
            for (int q = 0; q < 4; q++) { dm[i][j][q] = 0.f; dl[i][j][q] = 0.f; }

    float4 xv[4];
    uint4  bvh[2], bvl[2];

    // gmem load macros (chunk c)
    #define LDG_CHUNK(c)                                                            \
        do {                                                                        \
            _Pragma("unroll")                                                       \
            for (int t = 0; t < 4; t++) {                                           \
                int idx = tid + t * 256, r = idx >> 3, kq = idx & 7;                \
                xv[t] = *reinterpret_cast<const float4*>(                           \
                    &x[(size_t)(row0 + r) * DIM + (c) * BK + kq * 4]);              \
            }                                                                       \
            _Pragma("unroll")                                                       \
            for (int t = 0; t < 2; t++) {                                           \
                int idx = tid + t * 256, n = idx >> 2, kq = idx & 3;                \
                bvh[t] = *reinterpret_cast<const uint4*>(                           \
                    &g_Wt_hi[(size_t)n * DIM + (c) * BK + kq * 8]);                 \
                bvl[t] = *reinterpret_cast<const uint4*>(                           \
                    &g_Wt_lo[(size_t)n * DIM + (c) * BK + kq * 8]);                 \
            }                                                                       \
        } while (0)

    #define STS_CHUNK()                                                             \
        do {                                                                        \
            _Pragma("unroll")                                                       \
            for (int t = 0; t < 4; t++) {                                           \
                int idx = tid + t * 256, r = idx >> 3, kq = idx & 7;                \
                float4 v = xv[t];                                                   \
                __half2 h01 = __floats2half2_rn(v.x, v.y);                          \
                __half2 h23 = __floats2half2_rn(v.z, v.w);                          \
                __half2 l01 = __floats2half2_rn(                                    \
                    (v.x - __half2float(__low2half(h01))) * LO_SCALE,               \
                    (v.y - __half2float(__high2half(h01))) * LO_SCALE);             \
                __half2 l23 = __floats2half2_rn(                                    \
                    (v.z - __half2float(__low2half(h23))) * LO_SCALE,               \
                    (v.w - __half2float(__high2half(h23))) * LO_SCALE);             \
                uint2 uh, ul;                                                       \
                uh.x = *(uint32_t*)&h01; uh.y = *(uint32_t*)&h23;                   \
                ul.x = *(uint32_t*)&l01; ul.y = *(uint32_t*)&l23;                   \
                *reinterpret_cast<uint2*>(&A_hi[r * LDH + kq * 4]) = uh;            \
                *reinterpret_cast<uint2*>(&A_lo[r * LDH + kq * 4]) = ul;            \
            }                                                                       \
            _Pragma("unroll")                                                       \
            for (int t = 0; t < 2; t++) {                                           \
                int idx = tid + t * 256, n = idx >> 2, kq = idx & 3;                \
                *reinterpret_cast<uint4*>(&B_hi[n * LDH + kq * 8]) = bvh[t];        \
                *reinterpret_cast<uint4*>(&B_lo[n * LDH + kq * 8]) = bvl[t];        \
            }                                                                       \
        } while (0)

    // prologue
    LDG_CHUNK(0);
    STS_CHUNK();
    LDG_CHUNK(1);
    __syncthreads();

    for (int c = 0; c < NCHUNK; c++) {
        // ---- compute chunk c ----
        #pragma unroll
        for (int ks = 0; ks < 2; ks++) {
            uint32_t ah[4][4], al[4][4], bh[4][2], bl[4][2];
            #pragma unroll
            for (int it = 0; it < 4; it++) {
                uint32_t off = (uint32_t)(it * 16 * LDH * 2 + ks * 32);
                LDSM_X4(ah[it][0], ah[it][1], ah[it][2], ah[it][3], aA + off);
                LDSM_X4(al[it][0], al[it][1], al[it][2], al[it][3], aAl + off);
            }
            #pragma unroll
            for (int jp = 0; jp < 2; jp++) {
                uint32_t off = (uint32_t)(jp * 16 * LDH * 2 + ks * 32);
                LDSM_X4(bh[jp*2][0], bh[jp*2][1], bh[jp*2+1][0], bh[jp*2+1][1], aB + off);
                LDSM_X4(bl[jp*2][0], bl[jp*2][1], bl[jp*2+1][0], bl[jp*2+1][1], aBl + off);
            }
            #pragma unroll
            for (int it = 0; it < 4; it++)
                #pragma unroll
                for (int jt = 0; jt < 4; jt++) {
                    MMA16816(dm[it][jt], ah[it], bh[jt]);
                    MMA16816(dl[it][jt], ah[it], bl[jt]);
                    MMA16816(dl[it][jt], al[it], bh[jt]);
                }
        }
        __syncthreads();
        if (c < NCHUNK - 1) {
            STS_CHUNK();
            if (c < NCHUNK - 2) LDG_CHUNK(c + 2);
            __syncthreads();
        }
    }

    // ---- accums -> stage[128][132] ----
    __syncthreads();   // all ldmatrix of last chunk done before overwriting pipe
    #pragma unroll
    for (int it = 0; it < 4; it++) {
        #pragma unroll
        for (int jt = 0; jt < 4; jt++) {
            int r  = wm * 64 + it * 16 + (lane >> 2);
            int cb = wn * 32 + jt * 8 + (lane & 3) * 2;
            float v0 = fmaf(dl[it][jt][0], INV_LO, dm[it][jt][0]);
            float v1 = fmaf(dl[it][jt][1], INV_LO, dm[it][jt][1]);
            float v2 = fmaf(dl[it][jt][2], INV_LO, dm[it][jt][2]);
            float v3 = fmaf(dl[it][jt][3], INV_LO, dm[it][jt][3]);
            *reinterpret_cast<float2*>(&stage[r * 132 + cb])       = make_float2(v0, v1);
            *reinterpret_cast<float2*>(&stage[(r + 8) * 132 + cb]) = make_float2(v2, v3);
        }
    }
    __syncthreads();

    // ---- epilogue: 8 warps x 16 rows, lane = expert pair ----
    const float br1 = br[lane],      br2 = br[lane + 32];
    const float bn1 = bn[lane],      bn2 = bn[lane + 32];
    float* out_em = out;
    float* out_rp = out + (size_t)N_TOK * NEXP;

    float impAcc1 = 0.f, impAcc2 = 0.f, ldAcc1 = 0.f, ldAcc2 = 0.f;

    for (int rr = 0; rr < 16; rr++) {
        const int r    = wid * 16 + rr;
        const int grow = row0 + r;

        float raw1 = stage[r * 132 + lane]      + br1;
        float raw2 = stage[r * 132 + 32 + lane] + br2;
        float nl1  = stage[r * 132 + 64 + lane] + bn1;
        float nl2  = stage[r * 132 + 96 + lane] + bn2;

        float std1 = fmaxf(nl1, 0.f) + log1pf(expf(-fabsf(nl1))) + 0.01f;
        float std2 = fmaxf(nl2, 0.f) + log1pf(expf(-fabsf(nl2))) + 0.01f;

        float ne1 = neps[(size_t)grow * NEXP + lane];
        float ne2 = neps[(size_t)grow * NEXP + 32 + lane];
        float g1  = gum[(size_t)grow * NEXP + lane];
        float g2  = gum[(size_t)grow * NEXP + 32 + lane];

        float noisy1 = raw1 + ne1 * std1;
        float noisy2 = raw2 + ne2 * std2;

        // top-9, exact jax.lax.top_k tie semantics (lower index first)
        unsigned long long k1 =
            ((unsigned long long)ordkey(noisy1) << 6) | (unsigned long long)(63 - lane);
        unsigned long long k2 =
            ((unsigned long long)ordkey(noisy2) << 6) | (unsigned long long)(31 - lane);
        float sel1 = 0.f, sel2 = 0.f, thr = 0.f;
        #pragma unroll
        for (int it = 0; it < KSEL; it++) {
            unsigned long long loc = (k1 > k2) ? k1 : k2;
            #pragma unroll
            for (int off = 16; off; off >>= 1) {
                unsigned long long o = __shfl_xor_sync(0xffffffffu, loc, off);
                if (o > loc) loc = o;
            }
            if (it == KSEL - 1) thr = ordinv((unsigned int)(loc >> 6));
            if (k1 == loc)      { sel1 = 1.f; k1 = 0ull; }
            else if (k2 == loc) { sel2 = 1.f; k2 = 0ull; }
        }

        float m  = warp_max_f(fmaxf(noisy1, noisy2));
        float e1 = expf(noisy1 - m), e2 = expf(noisy2 - m);
        float s  = warp_sum_f(e1 + e2);
        float rp1 = e1 / s, rp2 = e2 / s;

        float ng1 = noisy1 + g1, ng2 = noisy2 + g2;
        float mg  = warp_max_f(fmaxf(ng1, ng2));
        float f1  = expf(ng1 - mg), f2 = expf(ng2 - mg);
        float sg  = warp_sum_f(f1 + f2);
        float ms1 = f1 / sg, ms2 = f2 / sg;

        float mr  = warp_max_f(fmaxf(raw1, raw2));
        float q1  = expf(raw1 - mr), q2 = expf(raw2 - mr);
        float sr  = warp_sum_f(q1 + q2);
        impAcc1 += q1 / sr;
        impAcc2 += q2 / sr;

        float a1 = (thr - raw1) / std1 * ERF_SCALE;
        float a2 = (thr - raw2) / std2 * ERF_SCALE;
        ldAcc1 += 0.5f * erfcf(a1);
        ldAcc2 += 0.5f * erfcf(a2);

        size_t ob = (size_t)grow * NEXP;
        out_em[ob + lane]      = (sel1 - ms1) + ms1;
        out_em[ob + 32 + lane] = (sel2 - ms2) + ms2;
        out_rp[ob + lane]      = rp1;
        out_rp[ob + 32 + lane] = rp2;
    }

    atomicAdd(&imp_s[lane],      impAcc1);
    atomicAdd(&imp_s[lane + 32], impAcc2);
    atomicAdd(&ld_s[lane],       ldAcc1);
    atomicAdd(&ld_s[lane + 32],  ldAcc2);

    __syncthreads();
    float* out_imp  = out + (size_t)2 * N_TOK * NEXP;
    float* out_load = out_imp + NEXP;
    if (tid < NEXP)          atomicAdd(&out_imp[tid], imp_s[tid]);
    else if (tid < 2 * NEXP) atomicAdd(&out_load[tid - NEXP], ld_s[tid - NEXP]);
}

extern "C" void kernel_launch(void* const* d_in, const int* in_sizes, int n_in,
                              void* d_out, int out_size) {
    const float* x    = (const float*)d_in[0];
    const float* Wr   = (const float*)d_in[1];
    const float* br   = (const float*)d_in[2];
    const float* Wn   = (const float*)d_in[3];
    const float* bn   = (const float*)d_in[4];
    const float* neps = (const float*)d_in[5];
    const float* gum  = (const float*)d_in[6];
    float* out = (float*)d_out;
    (void)in_sizes; (void)n_in; (void)out_size;

    static int attr_set = 0;
    if (!attr_set) {
        cudaFuncSetAttribute(moe_router_mma,
                             cudaFuncAttributeMaxDynamicSharedMemorySize, SMEM_DYN_BYTES);
        attr_set = 1;
    }

    prep_w_kernel<<<(128 * DIM) / 256, 256>>>(Wr, Wn);
    zero_tail_kernel<<<1, 128>>>(out + (size_t)2 * N_TOK * NEXP);
    moe_router_mma<<<N_TOK / 128, 256, SMEM_DYN_BYTES>>>(x, br, bn, neps, gum, out);
}

// round 16
// speedup vs baseline: 1.1715x; 1.1644x over previous
#include <cuda_runtime.h>
#include <cuda_fp16.h>
#include <cstdint>

#define N_TOK 16384
#define DIM   2048
#define NEXP  64
#define KSEL  9
#define ERF_SCALE 45.25483399593904f   // 64/sqrt(2)

#define BK      32
#define NCHUNK  (DIM / BK)             // 64
#define LDH     40                     // smem row stride in halves (80B)
#define ATILE_H (128 * LDH)            // halves per operand tile (5120)
#define BUFB    (4 * ATILE_H * 2)      // bytes per pipeline stage (40960)
#define LO_SCALE   2048.0f
#define INV_LO     (1.0f / 2048.0f)

// pipe: 2 stages x 40960B = 81920; stage overlay: 128*132*4 = 67584
#define SMEM_DYN_BYTES 81920

// pre-transposed, fp16-split W: [n][k], n: 0..63 Wr, 64..127 Wn. lo scaled by 2048.
__device__ __half g_Wt_hi[128 * DIM];
__device__ __half g_Wt_lo[128 * DIM];

// ---------------- helpers ----------------
__device__ __forceinline__ uint32_t smem_u32(const void* p) {
    return (uint32_t)__cvta_generic_to_shared((void*)p);
}

#define LDSM_X4(r0, r1, r2, r3, addr) \
    asm volatile("ldmatrix.sync.aligned.m8n8.x4.shared.b16 {%0,%1,%2,%3}, [%4];" \
        : "=r"(r0), "=r"(r1), "=r"(r2), "=r"(r3) : "r"(addr))

#define MMA16816(d, a, b) \
    asm volatile("mma.sync.aligned.m16n8k16.row.col.f32.f16.f16.f32 " \
        "{%0,%1,%2,%3}, {%4,%5,%6,%7}, {%8,%9}, {%0,%1,%2,%3};" \
        : "+f"((d)[0]), "+f"((d)[1]), "+f"((d)[2]), "+f"((d)[3]) \
        : "r"((a)[0]), "r"((a)[1]), "r"((a)[2]), "r"((a)[3]), \
          "r"((b)[0]), "r"((b)[1]))

__device__ __forceinline__ unsigned int ordkey(float f) {
    unsigned int b = __float_as_uint(f);
    return (b & 0x80000000u) ? ~b : (b | 0x80000000u);
}
__device__ __forceinline__ float ordinv(unsigned int u) {
    return __uint_as_float((u & 0x80000000u) ? (u ^ 0x80000000u) : ~u);
}
__device__ __forceinline__ float warp_max_f(float v) {
    #pragma unroll
    for (int off = 16; off; off >>= 1) v = fmaxf(v, __shfl_xor_sync(0xffffffffu, v, off));
    return v;
}
__device__ __forceinline__ float warp_sum_f(float v) {
    #pragma unroll
    for (int off = 16; off; off >>= 1) v += __shfl_xor_sync(0xffffffffu, v, off);
    return v;
}

// ---------------- prep kernel (coalesced writes + tail zero fold) ----------------
// 256 blocks x 256 threads; thread -> (n = idx>>9, k4 = (idx&511)*4).
__global__ void prep_w_kernel(const float* __restrict__ Wr, const float* __restrict__ Wn,
                              float* __restrict__ tail) {
    if (blockIdx.x == 0 && threadIdx.x < 128) tail[threadIdx.x] = 0.0f;
    int idx = blockIdx.x * 256 + threadIdx.x;          // 0..65535
    int n  = idx >> 9;                                 // 0..127
    int k4 = (idx & 511) << 2;                         // 0..2044 step 4
    const float* W = (n < 64) ? (Wr + n) : (Wn + (n - 64));
    __half h[4], l[4];
    #pragma unroll
    for (int i = 0; i < 4; i++) {
        float w = W[(size_t)(k4 + i) * NEXP];
        h[i] = __float2half_rn(w);
        l[i] = __float2half_rn((w - __half2float(h[i])) * LO_SCALE);
    }
    __half2 h01 = __halves2half2(h[0], h[1]), h23 = __halves2half2(h[2], h[3]);
    __half2 l01 = __halves2half2(l[0], l[1]), l23 = __halves2half2(l[2], l[3]);
    uint2 uh, ul;
    uh.x = *(uint32_t*)&h01; uh.y = *(uint32_t*)&h23;
    ul.x = *(uint32_t*)&l01; ul.y = *(uint32_t*)&l23;
    *reinterpret_cast<uint2*>(&g_Wt_hi[(size_t)n * DIM + k4]) = uh;
    *reinterpret_cast<uint2*>(&g_Wt_lo[(size_t)n * DIM + k4]) = ul;
}

// ---------------- main fused kernel ----------------
__global__ __launch_bounds__(256, 1)
void moe_router_mma(const float* __restrict__ x,
                    const float* __restrict__ br,
                    const float* __restrict__ bn,
                    const float* __restrict__ neps,
                    const float* __restrict__ gum,
                    float* __restrict__ out)
{
    extern __shared__ __align__(128) char dyn_smem[];
    __shared__ float imp_s[NEXP], ld_s[NEXP];

    float* stage = (float*)dyn_smem;                  // reused post-GEMM: [128][132]

    const int tid  = threadIdx.x;
    const int lane = tid & 31;
    const int wid  = tid >> 5;
    const int wm   = wid & 1;        // row half (64 rows)
    const int wn   = wid >> 1;       // col quarter (32 cols)
    const int row0 = blockIdx.x * 128;

    if (tid < NEXP)          imp_s[tid] = 0.0f;
    else if (tid < 2 * NEXP) ld_s[tid - NEXP] = 0.0f;

    // per-lane ldmatrix base addresses within stage-0 buffer (bytes, shared space)
    const int grp = lane >> 3, li = lane & 7;
    const uint32_t smem_base = smem_u32(dyn_smem);
    const uint32_t aA0 = smem_base +
        (uint32_t)(((wm * 64 + (grp & 1) * 8 + li) * LDH + (grp >> 1) * 8) * 2);
    const uint32_t aB0 = smem_base + (uint32_t)(2 * ATILE_H * 2) +
        (uint32_t)(((wn * 32 + (grp >> 1) * 8 + li) * LDH + (grp & 1) * 8) * 2);

    float dm[4][4][4], dl[4][4][4];
    #pragma unroll
    for (int i = 0; i < 4; i++)
        #pragma unroll
        for (int j = 0; j < 4; j++)
            #pragma unroll
            for (int q = 0; q < 4; q++) { dm[i][j][q] = 0.f; dl[i][j][q] = 0.f; }

    float4 xv[4];
    uint4  bvh[2], bvl[2];

    #define LDG_CHUNK(c)                                                            \
        do {                                                                        \
            _Pragma("unroll")                                                       \
            for (int t = 0; t < 4; t++) {                                           \
                int idx = tid + t * 256, r = idx >> 3, kq = idx & 7;                \
                xv[t] = *reinterpret_cast<const float4*>(                           \
                    &x[(size_t)(row0 + r) * DIM + (c) * BK + kq * 4]);              \
            }                                                                       \
            _Pragma("unroll")                                                       \
            for (int t = 0; t < 2; t++) {                                           \
                int idx = tid + t * 256, n = idx >> 2, kq = idx & 3;                \
                bvh[t] = *reinterpret_cast<const uint4*>(                           \
                    &g_Wt_hi[(size_t)n * DIM + (c) * BK + kq * 8]);                 \
                bvl[t] = *reinterpret_cast<const uint4*>(                           \
                    &g_Wt_lo[(size_t)n * DIM + (c) * BK + kq * 8]);                 \
            }                                                                       \
        } while (0)

    // ABASE: __half* to start of target pipeline stage
    #define STS_CHUNK(ABASE)                                                        \
        do {                                                                        \
            __half* A_hi_ = (ABASE);                                                \
            __half* A_lo_ = A_hi_ + ATILE_H;                                        \
            __half* B_hi_ = A_hi_ + 2 * ATILE_H;                                    \
            __half* B_lo_ = A_hi_ + 3 * ATILE_H;                                    \
            _Pragma("unroll")                                                       \
            for (int t = 0; t < 4; t++) {                                           \
                int idx = tid + t * 256, r = idx >> 3, kq = idx & 7;                \
                float4 v = xv[t];                                                   \
                __half2 h01 = __floats2half2_rn(v.x, v.y);                          \
                __half2 h23 = __floats2half2_rn(v.z, v.w);                          \
                __half2 l01 = __floats2half2_rn(                                    \
                    (v.x - __half2float(__low2half(h01))) * LO_SCALE,               \
                    (v.y - __half2float(__high2half(h01))) * LO_SCALE);             \
                __half2 l23 = __floats2half2_rn(                                    \
                    (v.z - __half2float(__low2half(h23))) * LO_SCALE,               \
                    (v.w - __half2float(__high2half(h23))) * LO_SCALE);             \
                uint2 uh, ul;                                                       \
                uh.x = *(uint32_t*)&h01; uh.y = *(uint32_t*)&h23;                   \
                ul.x = *(uint32_t*)&l01; ul.y = *(uint32_t*)&l23;                   \
                *reinterpret_cast<uint2*>(&A_hi_[r * LDH + kq * 4]) = uh;           \
                *reinterpret_cast<uint2*>(&A_lo_[r * LDH + kq * 4]) = ul;           \
            }                                                                       \
            _Pragma("unroll")                                                       \
            for (int t = 0; t < 2; t++) {                                           \
                int idx = tid + t * 256, n = idx >> 2, kq = idx & 3;                \
                *reinterpret_cast<uint4*>(&B_hi_[n * LDH + kq * 8]) = bvh[t];       \
                *reinterpret_cast<uint4*>(&B_lo_[n * LDH + kq * 8]) = bvl[t];       \
            }                                                                       \
        } while (0)

    #define LDSM_KS(ks, bo, ah, al, bh, bl)                                         \
        do {                                                                        \
            _Pragma("unroll")                                                       \
            for (int it = 0; it < 4; it++) {                                        \
                uint32_t off = (bo) + (uint32_t)(it * 16 * LDH * 2 + (ks) * 32);    \
                LDSM_X4(ah[it][0], ah[it][1], ah[it][2], ah[it][3], aA0 + off);     \
                uint32_t offl = off + (uint32_t)(ATILE_H * 2);                      \
                LDSM_X4(al[it][0], al[it][1], al[it][2], al[it][3], aA0 + offl);    \
            }                                                                       \
            _Pragma("unroll")                                                       \
            for (int jp = 0; jp < 2; jp++) {                                        \
                uint32_t off = (bo) + (uint32_t)(jp * 16 * LDH * 2 + (ks) * 32);    \
                LDSM_X4(bh[jp*2][0], bh[jp*2][1], bh[jp*2+1][0], bh[jp*2+1][1],     \
                        aB0 + off);                                                 \
                uint32_t offl = off + (uint32_t)(ATILE_H * 2);                      \
                LDSM_X4(bl[jp*2][0], bl[jp*2][1], bl[jp*2+1][0], bl[jp*2+1][1],     \
                        aB0 + offl);                                                \
            }                                                                       \
        } while (0)

    #define MMA_KS(ah, al, bh, bl)                                                  \
        do {                                                                        \
            _Pragma("unroll")                                                       \
            for (int it = 0; it < 4; it++)                                          \
                _Pragma("unroll")                                                   \
                for (int jt = 0; jt < 4; jt++) {                                    \
                    MMA16816(dm[it][jt], ah[it], bh[jt]);                           \
                    MMA16816(dl[it][jt], ah[it], bl[jt]);                           \
                    MMA16816(dl[it][jt], al[it], bh[jt]);                           \
                }                                                                   \
        } while (0)

    // prologue: chunk 0 -> stage 0; chunk 1 staged in regs
    LDG_CHUNK(0);
    STS_CHUNK((__half*)dyn_smem);
    LDG_CHUNK(1);
    __syncthreads();

    for (int c = 0; c < NCHUNK; c++) {
        const uint32_t bo = (uint32_t)((c & 1) * BUFB);
        __half* other = (__half*)(dyn_smem + ((c + 1) & 1) * BUFB);

        uint32_t ah[4][4], al[4][4], bh[4][2], bl[4][2];

        LDSM_KS(0, bo, ah, al, bh, bl);
        if (c < NCHUNK - 1) STS_CHUNK(other);      // drain under MMA shadow
        MMA_KS(ah, al, bh, bl);

        LDSM_KS(1, bo, ah, al, bh, bl);
        if (c < NCHUNK - 2) LDG_CHUNK(c + 2);      // prefetch next-next into regs
        MMA_KS(ah, al, bh, bl);

        __syncthreads();                           // stage (c+1) ready; buf c reusable
    }

    // ---- accums -> stage[128][132] ----
    #pragma unroll
    for (int it = 0; it < 4; it++) {
        #pragma unroll
        for (int jt = 0; jt < 4; jt++) {
            int r  = wm * 64 + it * 16 + (lane >> 2);
            int cb = wn * 32 + jt * 8 + (lane & 3) * 2;
            float v0 = fmaf(dl[it][jt][0], INV_LO, dm[it][jt][0]);
            float v1 = fmaf(dl[it][jt][1], INV_LO, dm[it][jt][1]);
            float v2 = fmaf(dl[it][jt][2], INV_LO, dm[it][jt][2]);
            float v3 = fmaf(dl[it][jt][3], INV_LO, dm[it][jt][3]);
            *reinterpret_cast<float2*>(&stage[r * 132 + cb])       = make_float2(v0, v1);
            *reinterpret_cast<float2*>(&stage[(r + 8) * 132 + cb]) = make_float2(v2, v3);
        }
    }
    __syncthreads();

    // ---- epilogue: 8 warps x 16 rows, lane = expert pair ----
    const float br1 = br[lane],      br2 = br[lane + 32];
    const float bn1 = bn[lane],      bn2 = bn[lane + 32];
    float* out_em = out;
    float* out_rp = out + (size_t)N_TOK * NEXP;

    float impAcc1 = 0.f, impAcc2 = 0.f, ldAcc1 = 0.f, ldAcc2 = 0.f;

    for (int rr = 0; rr < 16; rr++) {
        const int r    = wid * 16 + rr;
        const int grow = row0 + r;

        float raw1 = stage[r * 132 + lane]      + br1;
        float raw2 = stage[r * 132 + 32 + lane] + br2;
        float nl1  = stage[r * 132 + 64 + lane] + bn1;
        float nl2  = stage[r * 132 + 96 + lane] + bn2;

        float std1 = fmaxf(nl1, 0.f) + log1pf(expf(-fabsf(nl1))) + 0.01f;
        float std2 = fmaxf(nl2, 0.f) + log1pf(expf(-fabsf(nl2))) + 0.01f;

        float ne1 = neps[(size_t)grow * NEXP + lane];
        float ne2 = neps[(size_t)grow * NEXP + 32 + lane];
        float g1  = gum[(size_t)grow * NEXP + lane];
        float g2  = gum[(size_t)grow * NEXP + 32 + lane];

        float noisy1 = raw1 + ne1 * std1;
        float noisy2 = raw2 + ne2 * std2;

        // top-9, exact jax.lax.top_k tie semantics (lower index first)
        unsigned long long k1 =
            ((unsigned long long)ordkey(noisy1) << 6) | (unsigned long long)(63 - lane);
        unsigned long long k2 =
            ((unsigned long long)ordkey(noisy2) << 6) | (unsigned long long)(31 - lane);
        float sel1 = 0.f, sel2 = 0.f, thr = 0.f;
        #pragma unroll
        for (int it = 0; it < KSEL; it++) {
            unsigned long long loc = (k1 > k2) ? k1 : k2;
            #pragma unroll
            for (int off = 16; off; off >>= 1) {
                unsigned long long o = __shfl_xor_sync(0xffffffffu, loc, off);
                if (o > loc) loc = o;
            }
            if (it == KSEL - 1) thr = ordinv((unsigned int)(loc >> 6));
            if (k1 == loc)      { sel1 = 1.f; k1 = 0ull; }
            else if (k2 == loc) { sel2 = 1.f; k2 = 0ull; }
        }

        float m  = warp_max_f(fmaxf(noisy1, noisy2));
        float e1 = expf(noisy1 - m), e2 = expf(noisy2 - m);
        float s  = warp_sum_f(e1 + e2);
        float rp1 = e1 / s, rp2 = e2 / s;

        float ng1 = noisy1 + g1, ng2 = noisy2 + g2;
        float mg  = warp_max_f(fmaxf(ng1, ng2));
        float f1  = expf(ng1 - mg), f2 = expf(ng2 - mg);
        float sg  = warp_sum_f(f1 + f2);
        float ms1 = f1 / sg, ms2 = f2 / sg;

        float mr  = warp_max_f(fmaxf(raw1, raw2));
        float q1  = expf(raw1 - mr), q2 = expf(raw2 - mr);
        float sr  = warp_sum_f(q1 + q2);
        impAcc1 += q1 / sr;
        impAcc2 += q2 / sr;

        float a1 = (thr - raw1) / std1 * ERF_SCALE;
        float a2 = (thr - raw2) / std2 * ERF_SCALE;
        ldAcc1 += 0.5f * erfcf(a1);
        ldAcc2 += 0.5f * erfcf(a2);

        size_t ob = (size_t)grow * NEXP;
        out_em[ob + lane]      = (sel1 - ms1) + ms1;
        out_em[ob + 32 + lane] = (sel2 - ms2) + ms2;
        out_rp[ob + lane]      = rp1;
        out_rp[ob + 32 + lane] = rp2;
    }

    atomicAdd(&imp_s[lane],      impAcc1);
    atomicAdd(&imp_s[lane + 32], impAcc2);
    atomicAdd(&ld_s[lane],       ldAcc1);
    atomicAdd(&ld_s[lane + 32],  ldAcc2);

    __syncthreads();
    float* out_imp  = out + (size_t)2 * N_TOK * NEXP;
    float* out_load = out_imp + NEXP;
    if (tid < NEXP)          atomicAdd(&out_imp[tid], imp_s[tid]);
    else if (tid < 2 * NEXP) atomicAdd(&out_load[tid - NEXP], ld_s[tid - NEXP]);
}

extern "C" void kernel_launch(void* const* d_in, const int* in_sizes, int n_in,
                              void* d_out, int out_size) {
    const float* x    = (const float*)d_in[0];
    const float* Wr   = (const float*)d_in[1];
    const float* br   = (const float*)d_in[2];
    const float* Wn   = (const float*)d_in[3];
    const float* bn   = (const float*)d_in[4];
    const float* neps = (const float*)d_in[5];
    const float* gum  = (const float*)d_in[6];
    float* out = (float*)d_out;
    (void)in_sizes; (void)n_in; (void)out_size;

    static int attr_set = 0;
    if (!attr_set) {
        cudaFuncSetAttribute(moe_router_mma,
                             cudaFuncAttributeMaxDynamicSharedMemorySize, SMEM_DYN_BYTES);
        attr_set = 1;
    }

    prep_w_kernel<<<256, 256>>>(Wr, Wn, out + (size_t)2 * N_TOK * NEXP);
    moe_router_mma<<<N_TOK / 128, 256, SMEM_DYN_BYTES>>>(x, br, bn, neps, gum, out);
}